// round 13
// baseline (speedup 1.0000x reference)
#include <cuda_runtime.h>
#include <cuda_fp16.h>
#include <math.h>
#include <stdint.h>

typedef unsigned long long ull;

// Problem constants (fixed shapes)
#define NTOK   4096
#define NHEAD  8
#define NSAMP  27
#define CDIM   512
#define QKVW   1536

// -------- scratch (device globals; no allocations allowed) --------
// g_qkv row layout (6144 B): q fp32 [0,2048) | k fp16 [4096,5120) | v fp16 [5120,6144)
__device__ float  g_qkv[NTOK * QKVW];
__device__ float  g_off[NHEAD * NTOK * 81];      // offsets per (h,n)
__device__ float  g_ao [NTOK * CDIM];            // attention output fp32
__device__ float  g_pos[3 * NHEAD * NTOK * 28];  // pos-emb, 27-sample windows

// Packed fp32x2 FMA (Blackwell): d = a*b + d
#define FMA2(d, a, b) \
    asm("fma.rn.f32x2 %0, %1, %2, %0;" : "+l"(d) : "l"(a), "l"(b))
#define PACK2(d, s) \
    asm("mov.b64 %0, {%1, %1};" : "=l"(d) : "f"(s))

union F4U { float4 f; ull u[2]; };

// ============================================================
// sgemm_v1 (R10-proven): C[M,N] = A[M,K] @ W[N,K]^T (+ bias)
// BM=128, BK=8, 256 thr; A k-major non-dup smem + register PACK2.
// emit16: tiles with n0 >= 512 store fp16 packed at row-byte 4096+(col-512)*2.
// ============================================================
__global__ void __launch_bounds__(256, 2) sgemm_v1(
    const float* __restrict__ A, const float* __restrict__ W,
    const float* __restrict__ bias, float* __restrict__ C,
    int N, int K, int emit16)
{
    constexpr int MT = 8, AL = 4, TPR = 2, SA = 132;

    __shared__ __align__(16) float As[2][8][SA];
    __shared__ __align__(16) float Ws[2][8][132];

    const int tid = threadIdx.x;
    const int tx = tid & 15;
    const int ty = tid >> 4;
    const int m0 = blockIdx.y * 128, n0 = blockIdx.x * 128;
    const int alr = tid / TPR;
    const int alk = (tid % TPR) * AL;
    const int wlr = tid >> 1, wlk = (tid & 1) * 4;

    const float* Ap = A + (size_t)(m0 + alr) * K + alk;
    const float* Wp = W + (size_t)(n0 + wlr) * K + wlk;

    ull acc[MT][4];
#pragma unroll
    for (int i = 0; i < MT; i++)
#pragma unroll
        for (int j = 0; j < 4; j++) acc[i][j] = 0ULL;

    float ar[AL]; float4 wv;
    {
        float4 t = *(const float4*)Ap;
        ar[0] = t.x; ar[1] = t.y; ar[2] = t.z; ar[3] = t.w;
        wv = *(const float4*)Wp;
#pragma unroll
        for (int i = 0; i < AL; i++)
            As[0][alk + i][alr] = ar[i];
        Ws[0][wlk + 0][wlr] = wv.x; Ws[0][wlk + 1][wlr] = wv.y;
        Ws[0][wlk + 2][wlr] = wv.z; Ws[0][wlk + 3][wlr] = wv.w;
    }
    __syncthreads();

    const int nst = K >> 3;
    for (int st = 0; st < nst; st++) {
        const int buf = st & 1;
        const bool has = (st + 1) < nst;
        float ar2[AL]; float4 wv2;
        if (has) {
            float4 t = *(const float4*)(Ap + (st + 1) * 8);
            ar2[0] = t.x; ar2[1] = t.y; ar2[2] = t.z; ar2[3] = t.w;
            wv2 = *(const float4*)(Wp + (st + 1) * 8);
        }
#pragma unroll
        for (int kk = 0; kk < 8; kk++) {
            float af[MT];
            *(float4*)&af[0] = *(const float4*)&As[buf][kk][ty * MT];
            *(float4*)&af[4] = *(const float4*)&As[buf][kk][ty * MT + 4];
            ull a2[MT];
#pragma unroll
            for (int i = 0; i < MT; i++) PACK2(a2[i], af[i]);
            ulonglong2 q0 = *(const ulonglong2*)&Ws[buf][kk][tx * 8];
            ulonglong2 q1 = *(const ulonglong2*)&Ws[buf][kk][tx * 8 + 4];
            ull b2[4] = {q0.x, q0.y, q1.x, q1.y};
#pragma unroll
            for (int i = 0; i < MT; i++) {
                FMA2(acc[i][0], a2[i], b2[0]);
                FMA2(acc[i][1], a2[i], b2[1]);
                FMA2(acc[i][2], a2[i], b2[2]);
                FMA2(acc[i][3], a2[i], b2[3]);
            }
        }
        if (has) {
            const int nb = buf ^ 1;
#pragma unroll
            for (int i = 0; i < AL; i++)
                As[nb][alk + i][alr] = ar2[i];
            Ws[nb][wlk + 0][wlr] = wv2.x; Ws[nb][wlk + 1][wlr] = wv2.y;
            Ws[nb][wlk + 2][wlr] = wv2.z; Ws[nb][wlk + 3][wlr] = wv2.w;
        }
        __syncthreads();
    }

    float bv[8];
#pragma unroll
    for (int j = 0; j < 8; j++)
        bv[j] = bias ? __ldg(bias + n0 + tx * 8 + j) : 0.f;

    const bool half_out = emit16 && (n0 >= 512);

#pragma unroll
    for (int i = 0; i < MT; i++) {
        union { ull u; float2 f; } p[4];
#pragma unroll
        for (int j = 0; j < 4; j++) p[j].u = acc[i][j];
        float4 o0, o1;
        o0.x = p[0].f.x + bv[0]; o0.y = p[0].f.y + bv[1];
        o0.z = p[1].f.x + bv[2]; o0.w = p[1].f.y + bv[3];
        o1.x = p[2].f.x + bv[4]; o1.y = p[2].f.y + bv[5];
        o1.z = p[3].f.x + bv[6]; o1.w = p[3].f.y + bv[7];
        const int row = m0 + ty * MT + i;
        if (!half_out) {
            float* cp = C + (size_t)row * N + n0 + tx * 8;
            *(float4*)cp = o0;
            *(float4*)(cp + 4) = o1;
        } else {
            union { __half2 h2[4]; uint4 u; } hv;
            hv.h2[0] = __float22half2_rn(make_float2(o0.x, o0.y));
            hv.h2[1] = __float22half2_rn(make_float2(o0.z, o0.w));
            hv.h2[2] = __float22half2_rn(make_float2(o1.x, o1.y));
            hv.h2[3] = __float22half2_rn(make_float2(o1.z, o1.w));
            char* rowb = (char*)C + (size_t)row * (N * 4);
            *(uint4*)(rowb + 4096 + ((n0 - 512) + tx * 8) * 2) = hv.u;
        }
    }
}

// ============================================================
// sgemm_v2<64,128> (R12-proven for proj): row-pair accumulators,
// W duplicated in smem, 128 threads, 4 CTAs/SM.
// ============================================================
template<int BN, int NTHR>
__global__ void __launch_bounds__(NTHR, (NTHR == 256 ? 2 : 4)) sgemm_v2(
    const float* __restrict__ A, const float* __restrict__ W,
    const float* __restrict__ bias, float* __restrict__ C,
    int N, int K, int emit16)
{
    constexpr int NTX  = BN / 8;
    constexpr int WROW = NTX * 20;
    constexpr int AL   = (NTHR == 256) ? 4 : 8;

    __shared__ __align__(16) float As[2][8][132];
    __shared__ __align__(16) float Ws[2][8][WROW];

    const int tid = threadIdx.x;
    const int tx = tid & (NTX - 1);
    const int ty = tid / NTX;
    const int m0 = blockIdx.y * 128, n0 = blockIdx.x * BN;

    const int alr = (NTHR == 256) ? (tid >> 1) : tid;
    const int alk = (NTHR == 256) ? ((tid & 1) * 4) : 0;
    const int wc  = tid >> 1;
    const int wk  = (tid & 1) * 4;
    const int wso = 2 * (wc & 7) + (wc >> 3) * 20;

    const float* Ap = A + (size_t)(m0 + alr) * K + alk;
    const float* Wp = W + (size_t)(n0 + wc) * K + wk;

    ull acc[4][8];
#pragma unroll
    for (int i = 0; i < 4; i++)
#pragma unroll
        for (int c = 0; c < 8; c++) acc[i][c] = 0ULL;

    float ar[AL]; float4 wv;
    {
        float4 t = *(const float4*)Ap;
        ar[0] = t.x; ar[1] = t.y; ar[2] = t.z; ar[3] = t.w;
        if (AL == 8) {
            float4 t2 = *(const float4*)(Ap + 4);
            ar[4] = t2.x; ar[5] = t2.y; ar[6] = t2.z; ar[7] = t2.w;
        }
        wv = *(const float4*)Wp;
#pragma unroll
        for (int i = 0; i < AL; i++)
            As[0][alk + i][alr] = ar[i];
        const float wvv[4] = {wv.x, wv.y, wv.z, wv.w};
#pragma unroll
        for (int i = 0; i < 4; i++)
            *(float2*)&Ws[0][wk + i][wso] = make_float2(wvv[i], wvv[i]);
    }
    __syncthreads();

    const int nst = K >> 3;
    for (int st = 0; st < nst; st++) {
        const int buf = st & 1;
        const bool has = (st + 1) < nst;
        float ar2[AL]; float4 wv2;
        if (has) {
            float4 t = *(const float4*)(Ap + (st + 1) * 8);
            ar2[0] = t.x; ar2[1] = t.y; ar2[2] = t.z; ar2[3] = t.w;
            if (AL == 8) {
                float4 t2 = *(const float4*)(Ap + (st + 1) * 8 + 4);
                ar2[4] = t2.x; ar2[5] = t2.y; ar2[6] = t2.z; ar2[7] = t2.w;
            }
            wv2 = *(const float4*)(Wp + (st + 1) * 8);
        }
#pragma unroll
        for (int kk = 0; kk < 8; kk++) {
            F4U a0, a1;
            a0.f = *(const float4*)&As[buf][kk][ty * 8];
            a1.f = *(const float4*)&As[buf][kk][ty * 8 + 4];
            const ull ap[4] = {a0.u[0], a0.u[1], a1.u[0], a1.u[1]};
            const float* wr = &Ws[buf][kk][tx * 20];
            F4U w0, w1, w2, w3;
            w0.f = *(const float4*)(wr + 0);
            w1.f = *(const float4*)(wr + 4);
            w2.f = *(const float4*)(wr + 8);
            w3.f = *(const float4*)(wr + 12);
            const ull wd[8] = {w0.u[0], w0.u[1], w1.u[0], w1.u[1],
                               w2.u[0], w2.u[1], w3.u[0], w3.u[1]};
#pragma unroll
            for (int i = 0; i < 4; i++)
#pragma unroll
                for (int c = 0; c < 8; c++)
                    FMA2(acc[i][c], ap[i], wd[c]);
        }
        if (has) {
            const int nb = buf ^ 1;
#pragma unroll
            for (int i = 0; i < AL; i++)
                As[nb][alk + i][alr] = ar2[i];
            const float wvv[4] = {wv2.x, wv2.y, wv2.z, wv2.w};
#pragma unroll
            for (int i = 0; i < 4; i++)
                *(float2*)&Ws[nb][wk + i][wso] = make_float2(wvv[i], wvv[i]);
        }
        __syncthreads();
    }

    float bv[8];
#pragma unroll
    for (int c = 0; c < 8; c++)
        bv[c] = bias ? __ldg(bias + n0 + tx * 8 + c) : 0.f;

    const int colb = n0 + tx * 8;

#pragma unroll
    for (int i = 0; i < 4; i++) {
        union { ull u; float2 f; } p[8];
#pragma unroll
        for (int c = 0; c < 8; c++) p[c].u = acc[i][c];
        float o0[8], o1[8];
#pragma unroll
        for (int c = 0; c < 8; c++) {
            o0[c] = p[c].f.x + bv[c];
            o1[c] = p[c].f.y + bv[c];
        }
        const int row = m0 + ty * 8 + 2 * i;
        float* cp0 = C + (size_t)row * N + colb;
        float* cp1 = cp0 + N;
        *(float4*)cp0       = make_float4(o0[0], o0[1], o0[2], o0[3]);
        *(float4*)(cp0 + 4) = make_float4(o0[4], o0[5], o0[6], o0[7]);
        *(float4*)cp1       = make_float4(o1[0], o1[1], o1[2], o1[3]);
        *(float4*)(cp1 + 4) = make_float4(o1[4], o1[5], o1[6], o1[7]);
    }
}

// ============================================================
// Offsets: g_off[(h*N+n)*81 + c] = sum_k x[n, h*64+k] * w_off[c, k]
// ============================================================
__global__ void __launch_bounds__(256) offset_kernel(
    const float* __restrict__ x, const float* __restrict__ w_off)
{
    __shared__ float sw[81 * 64];
    const int tid = threadIdx.x;
    for (int i = tid; i < 81 * 64 / 4; i += 256)
        ((float4*)sw)[i] = ((const float4*)w_off)[i];
    __syncthreads();

    const int g = blockIdx.x * 256 + tid;
    const int h = g & 7, n = g >> 3;

    float4 xr[16];
    const float4* xp = (const float4*)(x + (size_t)n * CDIM + h * 64);
#pragma unroll
    for (int i = 0; i < 16; i++) xr[i] = xp[i];

    float* op = g_off + ((size_t)h * NTOK + n) * 81;
    for (int c = 0; c < 81; c++) {
        const float4* wp = (const float4*)(sw + c * 64);
        float acc = 0.f;
#pragma unroll
        for (int i = 0; i < 16; i++) {
            float4 w4 = wp[i];
            acc = fmaf(w4.x, xr[i].x, acc);
            acc = fmaf(w4.y, xr[i].y, acc);
            acc = fmaf(w4.z, xr[i].z, acc);
            acc = fmaf(w4.w, xr[i].w, acc);
        }
        op[c] = acc;
    }
}

// ============================================================
// Positional-embedding precompute (27-sample windows only):
//   g_pos[((tbl*8+h)*NTOK + m)*28 + s] = q(h,m,:) . rel_tbl[15 - sel(m) + s]
// sel(m): tbl0 -> m&15, tbl1 -> (m>>4)&15, tbl2 -> (m>>8)&15.
// Attn then reads all three tables at plain index s (verified algebra).
// ============================================================
__global__ void __launch_bounds__(256) pos_kernel(
    const float* __restrict__ rel_d, const float* __restrict__ rel_h,
    const float* __restrict__ rel_w)
{
    __shared__ __align__(16) float srel[3 * 42 * 64];
    const int tid = threadIdx.x;
    {
        float4* s4 = (float4*)srel;
        const float4* rw4 = (const float4*)rel_w;
        const float4* rh4 = (const float4*)rel_h;
        const float4* rd4 = (const float4*)rel_d;
        for (int i = tid; i < 672; i += 256) {
            s4[i] = rw4[i];
            s4[672 + i] = rh4[i];
            s4[1344 + i] = rd4[i];
        }
    }
    __syncthreads();

    const int h = blockIdx.y;
    const int n = blockIdx.x * 256 + tid;
    const int sel[3] = {n & 15, (n >> 4) & 15, (n >> 8) & 15};

    float4 q[16];
    const float4* qp = (const float4*)(g_qkv + (size_t)n * QKVW + h * 64);
#pragma unroll
    for (int i = 0; i < 16; i++) q[i] = qp[i];

#pragma unroll
    for (int tbl = 0; tbl < 3; tbl++) {
        const float4* rl = (const float4*)(srel + tbl * 42 * 64);
        const int jbase = 15 - sel[tbl];
        float* dst = g_pos + ((size_t)(tbl * 8 + h) * NTOK + n) * 28;
        for (int s4i = 0; s4i < 7; s4i++) {
            float res[4];
#pragma unroll
            for (int jj = 0; jj < 4; jj++) {
                const int s = s4i * 4 + jj;
                float a = 0.f, b = 0.f, c = 0.f, d = 0.f;
                if (s < 27) {
                    const float4* rr = rl + (jbase + s) * 16;
#pragma unroll
                    for (int i = 0; i < 16; i++) {
                        float4 rv = rr[i];
                        a = fmaf(q[i].x, rv.x, a);
                        b = fmaf(q[i].y, rv.y, b);
                        c = fmaf(q[i].z, rv.z, c);
                        d = fmaf(q[i].w, rv.w, d);
                    }
                }
                res[jj] = (a + b) + (c + d);
            }
            float4 outv; outv.x = res[0]; outv.y = res[1];
            outv.z = res[2]; outv.w = res[3];
            *(float4*)(dst + s4i * 4) = outv;
        }
    }
}

// ============================================================
// Fused deformable attention (fp16 k+v packed in qkv rows) — R10-proven,
// pos reads switched to the 28-stride window tables.
// ============================================================
__device__ __forceinline__ void corner_setup(
    int z, int y, int x, int s, float soz, float soy, float sox,
    int idx[8], float w[8])
{
    const float pz = (float)(z + s / 9 - 1) + soz;
    const float py = (float)(y + (s / 3) % 3 - 1) + soy;
    const float px = (float)(x + s % 3 - 1) + sox;
    const float fz = floorf(pz), fy = floorf(py), fx = floorf(px);
    const float wz = pz - fz, wy = py - fy, wx = px - fx;
    const int iz = (int)fz, iy = (int)fy, ix = (int)fx;
    const int z0 = min(max(iz, 0), 15), z1 = min(max(iz + 1, 0), 15);
    const int y0 = min(max(iy, 0), 15), y1 = min(max(iy + 1, 0), 15);
    const int x0 = min(max(ix, 0), 15), x1 = min(max(ix + 1, 0), 15);
    const float wz0 = ((unsigned)iz < 16u) ? 1.f - wz : 0.f;
    const float wz1 = ((unsigned)(iz + 1) < 16u) ? wz : 0.f;
    const float wy0 = ((unsigned)iy < 16u) ? 1.f - wy : 0.f;
    const float wy1 = ((unsigned)(iy + 1) < 16u) ? wy : 0.f;
    const float wx0 = ((unsigned)ix < 16u) ? 1.f - wx : 0.f;
    const float wx1 = ((unsigned)(ix + 1) < 16u) ? wx : 0.f;
    idx[0] = (z0 * 16 + y0) * 16 + x0;  w[0] = wz0 * wy0 * wx0;
    idx[1] = (z0 * 16 + y0) * 16 + x1;  w[1] = wz0 * wy0 * wx1;
    idx[2] = (z0 * 16 + y1) * 16 + x0;  w[2] = wz0 * wy1 * wx0;
    idx[3] = (z0 * 16 + y1) * 16 + x1;  w[3] = wz0 * wy1 * wx1;
    idx[4] = (z1 * 16 + y0) * 16 + x0;  w[4] = wz1 * wy0 * wx0;
    idx[5] = (z1 * 16 + y0) * 16 + x1;  w[5] = wz1 * wy0 * wx1;
    idx[6] = (z1 * 16 + y1) * 16 + x0;  w[6] = wz1 * wy1 * wx0;
    idx[7] = (z1 * 16 + y1) * 16 + x1;  w[7] = wz1 * wy1 * wx1;
}

#define GREC 20   // floats per geometry record (80B)

__global__ void __launch_bounds__(256) attn_kernel()
{
    __shared__ __align__(16) float sgeo[8 * NSAMP * GREC];  // 17.3 KB
    const int tid = threadIdx.x;
    const int warp = tid >> 5;
    const int lane = tid & 31;
    const int n = blockIdx.x * 8 + warp;
    const int h = blockIdx.y;
    const int z = n >> 8, y = (n >> 4) & 15, x = n & 15;
    const int c0 = lane << 1;

    // ---- phase 1: lane-parallel geometry + pos ----
    float* grec = sgeo + warp * NSAMP * GREC;
    if (lane < NSAMP) {
        const float* offp = g_off + ((size_t)h * NTOK + n) * 81 + lane * 3;
        const float oz = offp[0], oy = offp[1], ox = offp[2];
        int idx[8]; float w[8];
        corner_setup(z, y, x, lane, oz, oy, ox, idx, w);
        const int nzx = (z * 16 + x) * 16 + y;
        const int nxz = (x * 16 + z) * 16 + y;
        const float pos =
            g_pos[((size_t)h * NTOK + n) * 28 + lane] +
            g_pos[((size_t)(8 + h) * NTOK + nzx) * 28 + lane] +
            g_pos[((size_t)(16 + h) * NTOK + nxz) * 28 + lane];
        float* r = grec + lane * GREC;
        *(float4*)(r + 0) = make_float4(w[0], w[1], w[2], w[3]);
        *(float4*)(r + 4) = make_float4(w[4], w[5], w[6], w[7]);
        int4 ka, kb4;
        ka.x  = idx[0] * 6144; ka.y  = idx[1] * 6144;
        ka.z  = idx[2] * 6144; ka.w  = idx[3] * 6144;
        kb4.x = idx[4] * 6144; kb4.y = idx[5] * 6144;
        kb4.z = idx[6] * 6144; kb4.w = idx[7] * 6144;
        *(int4*)(r + 8)  = ka;
        *(int4*)(r + 12) = kb4;
        r[16] = pos;
    }
    __syncwarp();

    // ---- phase 2: per-sample loop ----
    const float2 qa = *(const float2*)(g_qkv + (size_t)n * QKVW + h * 64 + c0);
    const char* kbase = (const char*)g_qkv + 4096 + (h * 64 + c0) * 2;

    float ssum = 0.f, a0 = 0.f, a1 = 0.f;

#pragma unroll 3
    for (int s = 0; s < NSAMP; s++) {
        const float* r = grec + s * GREC;
        const float4 wa = *(const float4*)(r + 0);
        const float4 wb = *(const float4*)(r + 4);
        const int4   ka = *(const int4*)(r + 8);
        const int4   kc4 = *(const int4*)(r + 12);
        const float pos = r[16];
        const float w[8] = {wa.x, wa.y, wa.z, wa.w, wb.x, wb.y, wb.z, wb.w};
        const int ko[8] = {ka.x, ka.y, ka.z, ka.w, kc4.x, kc4.y, kc4.z, kc4.w};

        __half2 kh[8], vh[8];
#pragma unroll
        for (int c = 0; c < 8; c++) {
            const char* p = kbase + ko[c];
            kh[c] = *(const __half2*)p;
            vh[c] = *(const __half2*)(p + 1024);
        }

        float part = 0.f;
#pragma unroll
        for (int c = 0; c < 8; c++) {
            const float2 kf = __half22float2(kh[c]);
            part = fmaf(w[c], fmaf(kf.x, qa.x, kf.y * qa.y), part);
        }

#pragma unroll
        for (int o = 16; o > 0; o >>= 1)
            part += __shfl_xor_sync(0xffffffffu, part, o);

        const float val = 0.125f * part + pos;
        const float pr = __expf(val);
        ssum += pr;

#pragma unroll
        for (int c = 0; c < 8; c++) {
            const float2 vf = __half22float2(vh[c]);
            const float pw = pr * w[c];
            a0 = fmaf(pw, vf.x, a0);
            a1 = fmaf(pw, vf.y, a1);
        }
    }

    const float inv = 1.f / ssum;
    float2 res; res.x = a0 * inv; res.y = a1 * inv;
    *(float2*)(g_ao + (size_t)n * CDIM + h * 64 + c0) = res;
}

// ============================================================
extern "C" void kernel_launch(void* const* d_in, const int* in_sizes, int n_in,
                              void* d_out, int out_size)
{
    const float* x      = (const float*)d_in[0];
    const float* w_qkv  = (const float*)d_in[1];
    const float* w_proj = (const float*)d_in[2];
    const float* b_proj = (const float*)d_in[3];
    const float* w_off  = (const float*)d_in[4];
    const float* rel_d  = (const float*)d_in[5];
    const float* rel_h  = (const float*)d_in[6];
    const float* rel_w  = (const float*)d_in[7];
    float* out = (float*)d_out;

    float *qkv_p, *ao_p;
    cudaGetSymbolAddress((void**)&qkv_p, g_qkv);
    cudaGetSymbolAddress((void**)&ao_p,  g_ao);

    // 1) per-head deformable offsets
    offset_kernel<<<NTOK * NHEAD / 256, 256>>>(x, w_off);

    // 2) qkv = x @ w_qkv^T; q fp32, k/v packed fp16 (v1, R10-proven)
    sgemm_v1<<<dim3(QKVW / 128, NTOK / 128), 256>>>(
        x, w_qkv, nullptr, qkv_p, QKVW, CDIM, 1);

    // 3) positional-embedding precompute (27-windows)
    pos_kernel<<<dim3(NTOK / 256, NHEAD), 256>>>(rel_d, rel_h, rel_w);

    // 4) fused deformable attention (ncu captures this launch)
    attn_kernel<<<dim3(NTOK / 8, NHEAD), 256>>>();

    // 5) out = attn_out @ w_proj^T + b_proj (v2<64,128>, R12-proven)
    sgemm_v2<64, 128><<<dim3(CDIM / 64, NTOK / 128), 128>>>(
        ao_p, w_proj, b_proj, out, CDIM, CDIM, 0);
}

// round 14
// speedup vs baseline: 1.1251x; 1.1251x over previous
#include <cuda_runtime.h>
#include <cuda_fp16.h>
#include <math.h>
#include <stdint.h>

typedef unsigned long long ull;

// Problem constants (fixed shapes)
#define NTOK   4096
#define NHEAD  8
#define NSAMP  27
#define CDIM   512
#define QKVW   1536

// -------- scratch (device globals; no allocations allowed) --------
// g_qkv row layout (6144 B): q fp32 [0,2048) | k fp16 [4096,5120) | v fp16 [5120,6144)
__device__ float  g_qkv  [NTOK * QKVW];
__device__ float  g_off  [NHEAD * NTOK * 81];      // offsets per (h,n)
__device__ float  g_ao   [NTOK * CDIM];            // attention output fp32
__device__ float  g_pos  [3 * NHEAD * NTOK * 44];  // pos-emb tables (44-stride)
__device__ float  g_projp[2 * NTOK * CDIM];        // proj split-k partials

// Packed fp32x2 FMA (Blackwell): d = a*b + d
#define FMA2(d, a, b) \
    asm("fma.rn.f32x2 %0, %1, %2, %0;" : "+l"(d) : "l"(a), "l"(b))
#define PACK2(d, s) \
    asm("mov.b64 %0, {%1, %1};" : "=l"(d) : "f"(s))

// ============================================================
// sgemm_v1 (R10-proven core + R11 z-split params):
// C[M,N] = A[M, zk..zk+K) @ W[N, zk..zk+K)^T ; zk = blockIdx.z * K.
// BM=128, BK=8, 256 thr; A k-major non-dup smem + register PACK2.
// emit16: tiles with n0 >= 512 store fp16 packed at row-byte 4096+(col-512)*2.
// ============================================================
__global__ void __launch_bounds__(256, 2) sgemm_v1(
    const float* __restrict__ A, const float* __restrict__ W,
    float* __restrict__ C, int N, int K, int lda, int ldw,
    size_t zofC, int emit16)
{
    constexpr int MT = 8, AL = 4, TPR = 2;

    __shared__ __align__(16) float As[2][8][132];
    __shared__ __align__(16) float Ws[2][8][132];

    const int tid = threadIdx.x;
    const int tx = tid & 15;
    const int ty = tid >> 4;
    const int m0 = blockIdx.y * 128, n0 = blockIdx.x * 128;
    const int zk = blockIdx.z * K;
    const int alr = tid / TPR;
    const int alk = (tid % TPR) * AL;
    const int wlr = tid >> 1, wlk = (tid & 1) * 4;

    const float* Ap = A + (size_t)(m0 + alr) * lda + alk + zk;
    const float* Wp = W + (size_t)(n0 + wlr) * ldw + wlk + zk;
    C += zofC * blockIdx.z;

    ull acc[MT][4];
#pragma unroll
    for (int i = 0; i < MT; i++)
#pragma unroll
        for (int j = 0; j < 4; j++) acc[i][j] = 0ULL;

    float ar[AL]; float4 wv;
    {
        float4 t = *(const float4*)Ap;
        ar[0] = t.x; ar[1] = t.y; ar[2] = t.z; ar[3] = t.w;
        wv = *(const float4*)Wp;
#pragma unroll
        for (int i = 0; i < AL; i++)
            As[0][alk + i][alr] = ar[i];
        Ws[0][wlk + 0][wlr] = wv.x; Ws[0][wlk + 1][wlr] = wv.y;
        Ws[0][wlk + 2][wlr] = wv.z; Ws[0][wlk + 3][wlr] = wv.w;
    }
    __syncthreads();

    const int nst = K >> 3;
    for (int st = 0; st < nst; st++) {
        const int buf = st & 1;
        const bool has = (st + 1) < nst;
        float ar2[AL]; float4 wv2;
        if (has) {
            float4 t = *(const float4*)(Ap + (st + 1) * 8);
            ar2[0] = t.x; ar2[1] = t.y; ar2[2] = t.z; ar2[3] = t.w;
            wv2 = *(const float4*)(Wp + (st + 1) * 8);
        }
#pragma unroll
        for (int kk = 0; kk < 8; kk++) {
            float af[MT];
            *(float4*)&af[0] = *(const float4*)&As[buf][kk][ty * MT];
            *(float4*)&af[4] = *(const float4*)&As[buf][kk][ty * MT + 4];
            ull a2[MT];
#pragma unroll
            for (int i = 0; i < MT; i++) PACK2(a2[i], af[i]);
            ulonglong2 q0 = *(const ulonglong2*)&Ws[buf][kk][tx * 8];
            ulonglong2 q1 = *(const ulonglong2*)&Ws[buf][kk][tx * 8 + 4];
            ull b2[4] = {q0.x, q0.y, q1.x, q1.y};
#pragma unroll
            for (int i = 0; i < MT; i++) {
                FMA2(acc[i][0], a2[i], b2[0]);
                FMA2(acc[i][1], a2[i], b2[1]);
                FMA2(acc[i][2], a2[i], b2[2]);
                FMA2(acc[i][3], a2[i], b2[3]);
            }
        }
        if (has) {
            const int nb = buf ^ 1;
#pragma unroll
            for (int i = 0; i < AL; i++)
                As[nb][alk + i][alr] = ar2[i];
            Ws[nb][wlk + 0][wlr] = wv2.x; Ws[nb][wlk + 1][wlr] = wv2.y;
            Ws[nb][wlk + 2][wlr] = wv2.z; Ws[nb][wlk + 3][wlr] = wv2.w;
        }
        __syncthreads();
    }

    const bool half_out = emit16 && (n0 >= 512);

#pragma unroll
    for (int i = 0; i < MT; i++) {
        union { ull u; float2 f; } p[4];
#pragma unroll
        for (int j = 0; j < 4; j++) p[j].u = acc[i][j];
        float4 o0, o1;
        o0.x = p[0].f.x; o0.y = p[0].f.y;
        o0.z = p[1].f.x; o0.w = p[1].f.y;
        o1.x = p[2].f.x; o1.y = p[2].f.y;
        o1.z = p[3].f.x; o1.w = p[3].f.y;
        const int row = m0 + ty * MT + i;
        if (!half_out) {
            float* cp = C + (size_t)row * N + n0 + tx * 8;
            *(float4*)cp = o0;
            *(float4*)(cp + 4) = o1;
        } else {
            union { __half2 h2[4]; uint4 u; } hv;
            hv.h2[0] = __float22half2_rn(make_float2(o0.x, o0.y));
            hv.h2[1] = __float22half2_rn(make_float2(o0.z, o0.w));
            hv.h2[2] = __float22half2_rn(make_float2(o1.x, o1.y));
            hv.h2[3] = __float22half2_rn(make_float2(o1.z, o1.w));
            char* rowb = (char*)C + (size_t)row * (N * 4);
            *(uint4*)(rowb + 4096 + ((n0 - 512) + tx * 8) * 2) = hv.u;
        }
    }
}

// ============================================================
// proj merge: out = partial0 + partial1 + bias  (float4-vectorized)
// ============================================================
__global__ void __launch_bounds__(256) proj_merge(
    const float* __restrict__ bias, float* __restrict__ out)
{
    const int i = blockIdx.x * 256 + threadIdx.x;   // float4 idx, 0..524287
    const float4 a = ((const float4*)g_projp)[i];
    const float4 b = ((const float4*)g_projp)[i + NTOK * CDIM / 4];
    const float4 bb = ((const float4*)bias)[i & 127];
    float4 o;
    o.x = a.x + b.x + bb.x;
    o.y = a.y + b.y + bb.y;
    o.z = a.z + b.z + bb.z;
    o.w = a.w + b.w + bb.w;
    ((float4*)out)[i] = o;
}

// ============================================================
// Offsets: g_off[(h*N+n)*81 + c] = sum_k x[n, h*64+k] * w_off[c, k]
// ============================================================
__global__ void __launch_bounds__(256) offset_kernel(
    const float* __restrict__ x, const float* __restrict__ w_off)
{
    __shared__ float sw[81 * 64];
    const int tid = threadIdx.x;
    for (int i = tid; i < 81 * 64 / 4; i += 256)
        ((float4*)sw)[i] = ((const float4*)w_off)[i];
    __syncthreads();

    const int g = blockIdx.x * 256 + tid;
    const int h = g & 7, n = g >> 3;

    float4 xr[16];
    const float4* xp = (const float4*)(x + (size_t)n * CDIM + h * 64);
#pragma unroll
    for (int i = 0; i < 16; i++) xr[i] = xp[i];

    float* op = g_off + ((size_t)h * NTOK + n) * 81;
    for (int c = 0; c < 81; c++) {
        const float4* wp = (const float4*)(sw + c * 64);
        float acc = 0.f;
#pragma unroll
        for (int i = 0; i < 16; i++) {
            float4 w4 = wp[i];
            acc = fmaf(w4.x, xr[i].x, acc);
            acc = fmaf(w4.y, xr[i].y, acc);
            acc = fmaf(w4.z, xr[i].z, acc);
            acc = fmaf(w4.w, xr[i].w, acc);
        }
        op[c] = acc;
    }
}

// ============================================================
// Positional-embedding precompute (R12-proven uniform-j, 44-stride):
//   g_pos[((tbl*8+h)*NTOK + n)*44 + j] = q(h,n,:) . rel_tbl[j,:]
// j uniform per iteration -> conflict-free broadcast LDS.
// ============================================================
__global__ void __launch_bounds__(256) pos_kernel(
    const float* __restrict__ rel_d, const float* __restrict__ rel_h,
    const float* __restrict__ rel_w)
{
    __shared__ __align__(16) float srel[3 * 42 * 64];
    const int tid = threadIdx.x;
    {
        float4* s4 = (float4*)srel;
        const float4* rw4 = (const float4*)rel_w;
        const float4* rh4 = (const float4*)rel_h;
        const float4* rd4 = (const float4*)rel_d;
        for (int i = tid; i < 672; i += 256) {
            s4[i] = rw4[i];
            s4[672 + i] = rh4[i];
            s4[1344 + i] = rd4[i];
        }
    }
    __syncthreads();

    const int h = blockIdx.y;
    const int n = blockIdx.x * 256 + tid;

    float4 q[16];
    const float4* qp = (const float4*)(g_qkv + (size_t)n * QKVW + h * 64);
#pragma unroll
    for (int i = 0; i < 16; i++) q[i] = qp[i];

    for (int tbl = 0; tbl < 3; tbl++) {
        const float4* rl = (const float4*)(srel + tbl * 42 * 64);
        float* dst = g_pos + ((size_t)(tbl * 8 + h) * NTOK + n) * 44;
        for (int j4 = 0; j4 < 11; j4++) {
            float res[4];
#pragma unroll
            for (int jj = 0; jj < 4; jj++) {
                const int j = j4 * 4 + jj;
                float a = 0.f, b = 0.f, c = 0.f, d = 0.f;
                if (j < 42) {
                    const float4* rr = rl + j * 16;
#pragma unroll
                    for (int i = 0; i < 16; i++) {
                        float4 rv = rr[i];
                        a = fmaf(q[i].x, rv.x, a);
                        b = fmaf(q[i].y, rv.y, b);
                        c = fmaf(q[i].z, rv.z, c);
                        d = fmaf(q[i].w, rv.w, d);
                    }
                }
                res[jj] = (a + b) + (c + d);
            }
            float4 outv; outv.x = res[0]; outv.y = res[1];
            outv.z = res[2]; outv.w = res[3];
            *(float4*)(dst + j4 * 4) = outv;
        }
    }
}

// ============================================================
// Fused deformable attention (fp16 k+v packed in qkv rows) — R10-proven.
// ============================================================
__device__ __forceinline__ void corner_setup(
    int z, int y, int x, int s, float soz, float soy, float sox,
    int idx[8], float w[8])
{
    const float pz = (float)(z + s / 9 - 1) + soz;
    const float py = (float)(y + (s / 3) % 3 - 1) + soy;
    const float px = (float)(x + s % 3 - 1) + sox;
    const float fz = floorf(pz), fy = floorf(py), fx = floorf(px);
    const float wz = pz - fz, wy = py - fy, wx = px - fx;
    const int iz = (int)fz, iy = (int)fy, ix = (int)fx;
    const int z0 = min(max(iz, 0), 15), z1 = min(max(iz + 1, 0), 15);
    const int y0 = min(max(iy, 0), 15), y1 = min(max(iy + 1, 0), 15);
    const int x0 = min(max(ix, 0), 15), x1 = min(max(ix + 1, 0), 15);
    const float wz0 = ((unsigned)iz < 16u) ? 1.f - wz : 0.f;
    const float wz1 = ((unsigned)(iz + 1) < 16u) ? wz : 0.f;
    const float wy0 = ((unsigned)iy < 16u) ? 1.f - wy : 0.f;
    const float wy1 = ((unsigned)(iy + 1) < 16u) ? wy : 0.f;
    const float wx0 = ((unsigned)ix < 16u) ? 1.f - wx : 0.f;
    const float wx1 = ((unsigned)(ix + 1) < 16u) ? wx : 0.f;
    idx[0] = (z0 * 16 + y0) * 16 + x0;  w[0] = wz0 * wy0 * wx0;
    idx[1] = (z0 * 16 + y0) * 16 + x1;  w[1] = wz0 * wy0 * wx1;
    idx[2] = (z0 * 16 + y1) * 16 + x0;  w[2] = wz0 * wy1 * wx0;
    idx[3] = (z0 * 16 + y1) * 16 + x1;  w[3] = wz0 * wy1 * wx1;
    idx[4] = (z1 * 16 + y0) * 16 + x0;  w[4] = wz1 * wy0 * wx0;
    idx[5] = (z1 * 16 + y0) * 16 + x1;  w[5] = wz1 * wy0 * wx1;
    idx[6] = (z1 * 16 + y1) * 16 + x0;  w[6] = wz1 * wy1 * wx0;
    idx[7] = (z1 * 16 + y1) * 16 + x1;  w[7] = wz1 * wy1 * wx1;
}

#define GREC 20   // floats per geometry record (80B)

__global__ void __launch_bounds__(256) attn_kernel()
{
    __shared__ __align__(16) float sgeo[8 * NSAMP * GREC];  // 17.3 KB
    const int tid = threadIdx.x;
    const int warp = tid >> 5;
    const int lane = tid & 31;
    const int n = blockIdx.x * 8 + warp;
    const int h = blockIdx.y;
    const int z = n >> 8, y = (n >> 4) & 15, x = n & 15;
    const int c0 = lane << 1;

    // ---- phase 1: lane-parallel geometry + pos ----
    float* grec = sgeo + warp * NSAMP * GREC;
    if (lane < NSAMP) {
        const float* offp = g_off + ((size_t)h * NTOK + n) * 81 + lane * 3;
        const float oz = offp[0], oy = offp[1], ox = offp[2];
        int idx[8]; float w[8];
        corner_setup(z, y, x, lane, oz, oy, ox, idx, w);
        const int j = 15 + lane - x;
        const int nzx = (z * 16 + x) * 16 + y;
        const int nxz = (x * 16 + z) * 16 + y;
        const float pos =
            g_pos[((size_t)h * NTOK + n) * 44 + j] +
            g_pos[((size_t)(8 + h) * NTOK + nzx) * 44 + j] +
            g_pos[((size_t)(16 + h) * NTOK + nxz) * 44 + j];
        float* r = grec + lane * GREC;
        *(float4*)(r + 0) = make_float4(w[0], w[1], w[2], w[3]);
        *(float4*)(r + 4) = make_float4(w[4], w[5], w[6], w[7]);
        int4 ka, kb4;
        ka.x  = idx[0] * 6144; ka.y  = idx[1] * 6144;
        ka.z  = idx[2] * 6144; ka.w  = idx[3] * 6144;
        kb4.x = idx[4] * 6144; kb4.y = idx[5] * 6144;
        kb4.z = idx[6] * 6144; kb4.w = idx[7] * 6144;
        *(int4*)(r + 8)  = ka;
        *(int4*)(r + 12) = kb4;
        r[16] = pos;
    }
    __syncwarp();

    // ---- phase 2: per-sample loop ----
    const float2 qa = *(const float2*)(g_qkv + (size_t)n * QKVW + h * 64 + c0);
    const char* kbase = (const char*)g_qkv + 4096 + (h * 64 + c0) * 2;

    float ssum = 0.f, a0 = 0.f, a1 = 0.f;

#pragma unroll 3
    for (int s = 0; s < NSAMP; s++) {
        const float* r = grec + s * GREC;
        const float4 wa = *(const float4*)(r + 0);
        const float4 wb = *(const float4*)(r + 4);
        const int4   ka = *(const int4*)(r + 8);
        const int4   kc4 = *(const int4*)(r + 12);
        const float pos = r[16];
        const float w[8] = {wa.x, wa.y, wa.z, wa.w, wb.x, wb.y, wb.z, wb.w};
        const int ko[8] = {ka.x, ka.y, ka.z, ka.w, kc4.x, kc4.y, kc4.z, kc4.w};

        __half2 kh[8], vh[8];
#pragma unroll
        for (int c = 0; c < 8; c++) {
            const char* p = kbase + ko[c];
            kh[c] = *(const __half2*)p;
            vh[c] = *(const __half2*)(p + 1024);
        }

        float part = 0.f;
#pragma unroll
        for (int c = 0; c < 8; c++) {
            const float2 kf = __half22float2(kh[c]);
            part = fmaf(w[c], fmaf(kf.x, qa.x, kf.y * qa.y), part);
        }

#pragma unroll
        for (int o = 16; o > 0; o >>= 1)
            part += __shfl_xor_sync(0xffffffffu, part, o);

        const float val = 0.125f * part + pos;
        const float pr = __expf(val);
        ssum += pr;

#pragma unroll
        for (int c = 0; c < 8; c++) {
            const float2 vf = __half22float2(vh[c]);
            const float pw = pr * w[c];
            a0 = fmaf(pw, vf.x, a0);
            a1 = fmaf(pw, vf.y, a1);
        }
    }

    const float inv = 1.f / ssum;
    float2 res; res.x = a0 * inv; res.y = a1 * inv;
    *(float2*)(g_ao + (size_t)n * CDIM + h * 64 + c0) = res;
}

// ============================================================
extern "C" void kernel_launch(void* const* d_in, const int* in_sizes, int n_in,
                              void* d_out, int out_size)
{
    const float* x      = (const float*)d_in[0];
    const float* w_qkv  = (const float*)d_in[1];
    const float* w_proj = (const float*)d_in[2];
    const float* b_proj = (const float*)d_in[3];
    const float* w_off  = (const float*)d_in[4];
    const float* rel_d  = (const float*)d_in[5];
    const float* rel_h  = (const float*)d_in[6];
    const float* rel_w  = (const float*)d_in[7];
    float* out = (float*)d_out;

    float *qkv_p, *ao_p, *pp_p;
    cudaGetSymbolAddress((void**)&qkv_p, g_qkv);
    cudaGetSymbolAddress((void**)&ao_p,  g_ao);
    cudaGetSymbolAddress((void**)&pp_p,  g_projp);

    // 1) per-head deformable offsets
    offset_kernel<<<NTOK * NHEAD / 256, 256>>>(x, w_off);

    // 2) qkv = x @ w_qkv^T; q fp32, k/v packed fp16 (full K, z=1)
    sgemm_v1<<<dim3(QKVW / 128, NTOK / 128, 1), 256>>>(
        x, w_qkv, qkv_p, QKVW, CDIM, CDIM, CDIM, 0, 1);

    // 3) positional-embedding precompute (uniform-j, conflict-free)
    pos_kernel<<<dim3(NTOK / 256, NHEAD), 256>>>(rel_d, rel_h, rel_w);

    // 4) fused deformable attention (ncu slot)
    attn_kernel<<<dim3(NTOK / 8, NHEAD), 256>>>();

    // 5) proj split-K=2: grid (4, 32, 2) = 256 CTAs -> 86% chip fill
    sgemm_v1<<<dim3(CDIM / 128, NTOK / 128, 2), 256>>>(
        ao_p, w_proj, pp_p, CDIM, CDIM / 2, CDIM, CDIM,
        (size_t)NTOK * CDIM, 0);

    // 6) merge partials + bias -> out
    proj_merge<<<NTOK * CDIM / 4 / 256, 256>>>(b_proj, out);
}

// round 15
// speedup vs baseline: 1.2214x; 1.0856x over previous
#include <cuda_runtime.h>
#include <cuda_fp16.h>
#include <math.h>
#include <stdint.h>

typedef unsigned long long ull;

// Problem constants (fixed shapes)
#define NTOK   4096
#define NHEAD  8
#define NSAMP  27
#define CDIM   512
#define QKVW   1536

// -------- scratch (device globals; no allocations allowed) --------
// g_qkv row layout (6144 B): q fp32 [0,2048) | k fp16 [4096,5120) | v fp16 [5120,6144)
__device__ float  g_qkv  [NTOK * QKVW];
__device__ float  g_off  [NHEAD * NTOK * 81];      // offsets per (h,n)
__device__ float  g_ao   [NTOK * CDIM];            // attention output fp32
__device__ float  g_pos  [3 * NHEAD * NTOK * 44];  // pos-emb tables (44-stride)
__device__ float  g_projp[2 * NTOK * CDIM];        // proj split-k partials

// Packed fp32x2 FMA (Blackwell): d = a*b + d
#define FMA2(d, a, b) \
    asm("fma.rn.f32x2 %0, %1, %2, %0;" : "+l"(d) : "l"(a), "l"(b))
#define PACK2(d, s) \
    asm("mov.b64 %0, {%1, %1};" : "=l"(d) : "f"(s))

// ============================================================
// qkv GEMM body (R10-proven v1 core), fused with offset kernel below.
// C = g_qkv; q fp32 cols [0,512), k/v fp16 packed cols [512,1536).
// ============================================================
__device__ __forceinline__ void qkv_body(
    const float* __restrict__ A, const float* __restrict__ W,
    int bx, int by)
{
    __shared__ __align__(16) float As[2][8][132];
    __shared__ __align__(16) float Ws[2][8][132];

    const int tid = threadIdx.x;
    const int tx = tid & 15;
    const int ty = tid >> 4;
    const int m0 = by * 128, n0 = bx * 128;
    const int alr = tid >> 1;
    const int alk = (tid & 1) * 4;
    const int wlr = tid >> 1, wlk = (tid & 1) * 4;

    const float* Ap = A + (size_t)(m0 + alr) * CDIM + alk;
    const float* Wp = W + (size_t)(n0 + wlr) * CDIM + wlk;
    float* C = g_qkv;

    ull acc[8][4];
#pragma unroll
    for (int i = 0; i < 8; i++)
#pragma unroll
        for (int j = 0; j < 4; j++) acc[i][j] = 0ULL;

    {
        float4 t = *(const float4*)Ap;
        float4 wv = *(const float4*)Wp;
        As[0][alk + 0][alr] = t.x; As[0][alk + 1][alr] = t.y;
        As[0][alk + 2][alr] = t.z; As[0][alk + 3][alr] = t.w;
        Ws[0][wlk + 0][wlr] = wv.x; Ws[0][wlk + 1][wlr] = wv.y;
        Ws[0][wlk + 2][wlr] = wv.z; Ws[0][wlk + 3][wlr] = wv.w;
    }
    __syncthreads();

    const int nst = CDIM >> 3;
    for (int st = 0; st < nst; st++) {
        const int buf = st & 1;
        const bool has = (st + 1) < nst;
        float4 t2, wv2;
        if (has) {
            t2 = *(const float4*)(Ap + (st + 1) * 8);
            wv2 = *(const float4*)(Wp + (st + 1) * 8);
        }
#pragma unroll
        for (int kk = 0; kk < 8; kk++) {
            float af[8];
            *(float4*)&af[0] = *(const float4*)&As[buf][kk][ty * 8];
            *(float4*)&af[4] = *(const float4*)&As[buf][kk][ty * 8 + 4];
            ull a2[8];
#pragma unroll
            for (int i = 0; i < 8; i++) PACK2(a2[i], af[i]);
            ulonglong2 q0 = *(const ulonglong2*)&Ws[buf][kk][tx * 8];
            ulonglong2 q1 = *(const ulonglong2*)&Ws[buf][kk][tx * 8 + 4];
            ull b2[4] = {q0.x, q0.y, q1.x, q1.y};
#pragma unroll
            for (int i = 0; i < 8; i++) {
                FMA2(acc[i][0], a2[i], b2[0]);
                FMA2(acc[i][1], a2[i], b2[1]);
                FMA2(acc[i][2], a2[i], b2[2]);
                FMA2(acc[i][3], a2[i], b2[3]);
            }
        }
        if (has) {
            const int nb = buf ^ 1;
            As[nb][alk + 0][alr] = t2.x; As[nb][alk + 1][alr] = t2.y;
            As[nb][alk + 2][alr] = t2.z; As[nb][alk + 3][alr] = t2.w;
            Ws[nb][wlk + 0][wlr] = wv2.x; Ws[nb][wlk + 1][wlr] = wv2.y;
            Ws[nb][wlk + 2][wlr] = wv2.z; Ws[nb][wlk + 3][wlr] = wv2.w;
        }
        __syncthreads();
    }

    const bool half_out = (n0 >= 512);

#pragma unroll
    for (int i = 0; i < 8; i++) {
        union { ull u; float2 f; } p[4];
#pragma unroll
        for (int j = 0; j < 4; j++) p[j].u = acc[i][j];
        float4 o0, o1;
        o0.x = p[0].f.x; o0.y = p[0].f.y;
        o0.z = p[1].f.x; o0.w = p[1].f.y;
        o1.x = p[2].f.x; o1.y = p[2].f.y;
        o1.z = p[3].f.x; o1.w = p[3].f.y;
        const int row = m0 + ty * 8 + i;
        if (!half_out) {
            float* cp = C + (size_t)row * QKVW + n0 + tx * 8;
            *(float4*)cp = o0;
            *(float4*)(cp + 4) = o1;
        } else {
            union { __half2 h2[4]; uint4 u; } hv;
            hv.h2[0] = __float22half2_rn(make_float2(o0.x, o0.y));
            hv.h2[1] = __float22half2_rn(make_float2(o0.z, o0.w));
            hv.h2[2] = __float22half2_rn(make_float2(o1.x, o1.y));
            hv.h2[3] = __float22half2_rn(make_float2(o1.z, o1.w));
            char* rowb = (char*)C + (size_t)row * (QKVW * 4);
            *(uint4*)(rowb + 4096 + ((n0 - 512) + tx * 8) * 2) = hv.u;
        }
    }
}

// ============================================================
// Offset body: g_off[(h*N+n)*81 + c] = sum_k x[n, h*64+k] * w_off[c, k]
// ============================================================
__device__ __forceinline__ void offset_body(
    const float* __restrict__ x, const float* __restrict__ w_off, int b)
{
    __shared__ float sw[81 * 64];
    const int tid = threadIdx.x;
    for (int i = tid; i < 81 * 64 / 4; i += 256)
        ((float4*)sw)[i] = ((const float4*)w_off)[i];
    __syncthreads();

    const int g = b * 256 + tid;
    const int h = g & 7, n = g >> 3;

    float4 xr[16];
    const float4* xp = (const float4*)(x + (size_t)n * CDIM + h * 64);
#pragma unroll
    for (int i = 0; i < 16; i++) xr[i] = xp[i];

    float* op = g_off + ((size_t)h * NTOK + n) * 81;
    for (int c = 0; c < 81; c++) {
        const float4* wp = (const float4*)(sw + c * 64);
        float acc = 0.f;
#pragma unroll
        for (int i = 0; i < 16; i++) {
            float4 w4 = wp[i];
            acc = fmaf(w4.x, xr[i].x, acc);
            acc = fmaf(w4.y, xr[i].y, acc);
            acc = fmaf(w4.z, xr[i].z, acc);
            acc = fmaf(w4.w, xr[i].w, acc);
        }
        op[c] = acc;
    }
}

// Fused launch: blocks 0..383 = qkv GEMM tiles (12 x 32), 384..511 = offsets.
__global__ void __launch_bounds__(256, 2) qkv_offset_kernel(
    const float* __restrict__ x, const float* __restrict__ w_qkv,
    const float* __restrict__ w_off)
{
    const int b = blockIdx.x;
    if (b < 384) {
        qkv_body(x, w_qkv, b % 12, b / 12);
    } else {
        offset_body(x, w_off, b - 384);
    }
}

// ============================================================
// proj GEMM (R14-proven sgemm_v1 with z-split) + merge
// ============================================================
__global__ void __launch_bounds__(256, 2) sgemm_proj(
    const float* __restrict__ A, const float* __restrict__ W,
    float* __restrict__ C)
{
    constexpr int K = CDIM / 2;

    __shared__ __align__(16) float As[2][8][132];
    __shared__ __align__(16) float Ws[2][8][132];

    const int tid = threadIdx.x;
    const int tx = tid & 15;
    const int ty = tid >> 4;
    const int m0 = blockIdx.y * 128, n0 = blockIdx.x * 128;
    const int zk = blockIdx.z * K;
    const int alr = tid >> 1;
    const int alk = (tid & 1) * 4;

    const float* Ap = A + (size_t)(m0 + alr) * CDIM + alk + zk;
    const float* Wp = W + (size_t)(n0 + alr) * CDIM + alk + zk;
    C += (size_t)NTOK * CDIM * blockIdx.z;

    ull acc[8][4];
#pragma unroll
    for (int i = 0; i < 8; i++)
#pragma unroll
        for (int j = 0; j < 4; j++) acc[i][j] = 0ULL;

    {
        float4 t = *(const float4*)Ap;
        float4 wv = *(const float4*)Wp;
        As[0][alk + 0][alr] = t.x; As[0][alk + 1][alr] = t.y;
        As[0][alk + 2][alr] = t.z; As[0][alk + 3][alr] = t.w;
        Ws[0][alk + 0][alr] = wv.x; Ws[0][alk + 1][alr] = wv.y;
        Ws[0][alk + 2][alr] = wv.z; Ws[0][alk + 3][alr] = wv.w;
    }
    __syncthreads();

    const int nst = K >> 3;
    for (int st = 0; st < nst; st++) {
        const int buf = st & 1;
        const bool has = (st + 1) < nst;
        float4 t2, wv2;
        if (has) {
            t2 = *(const float4*)(Ap + (st + 1) * 8);
            wv2 = *(const float4*)(Wp + (st + 1) * 8);
        }
#pragma unroll
        for (int kk = 0; kk < 8; kk++) {
            float af[8];
            *(float4*)&af[0] = *(const float4*)&As[buf][kk][ty * 8];
            *(float4*)&af[4] = *(const float4*)&As[buf][kk][ty * 8 + 4];
            ull a2[8];
#pragma unroll
            for (int i = 0; i < 8; i++) PACK2(a2[i], af[i]);
            ulonglong2 q0 = *(const ulonglong2*)&Ws[buf][kk][tx * 8];
            ulonglong2 q1 = *(const ulonglong2*)&Ws[buf][kk][tx * 8 + 4];
            ull b2[4] = {q0.x, q0.y, q1.x, q1.y};
#pragma unroll
            for (int i = 0; i < 8; i++) {
                FMA2(acc[i][0], a2[i], b2[0]);
                FMA2(acc[i][1], a2[i], b2[1]);
                FMA2(acc[i][2], a2[i], b2[2]);
                FMA2(acc[i][3], a2[i], b2[3]);
            }
        }
        if (has) {
            const int nb = buf ^ 1;
            As[nb][alk + 0][alr] = t2.x; As[nb][alk + 1][alr] = t2.y;
            As[nb][alk + 2][alr] = t2.z; As[nb][alk + 3][alr] = t2.w;
            Ws[nb][alk + 0][alr] = wv2.x; Ws[nb][alk + 1][alr] = wv2.y;
            Ws[nb][alk + 2][alr] = wv2.z; Ws[nb][alk + 3][alr] = wv2.w;
        }
        __syncthreads();
    }

#pragma unroll
    for (int i = 0; i < 8; i++) {
        union { ull u; float2 f; } p[4];
#pragma unroll
        for (int j = 0; j < 4; j++) p[j].u = acc[i][j];
        float4 o0, o1;
        o0.x = p[0].f.x; o0.y = p[0].f.y;
        o0.z = p[1].f.x; o0.w = p[1].f.y;
        o1.x = p[2].f.x; o1.y = p[2].f.y;
        o1.z = p[3].f.x; o1.w = p[3].f.y;
        float* cp = C + (size_t)(m0 + ty * 8 + i) * CDIM + n0 + tx * 8;
        *(float4*)cp = o0;
        *(float4*)(cp + 4) = o1;
    }
}

__global__ void __launch_bounds__(256) proj_merge(
    const float* __restrict__ bias, float* __restrict__ out)
{
    const int i = blockIdx.x * 256 + threadIdx.x;
    const float4 a = ((const float4*)g_projp)[i];
    const float4 b = ((const float4*)g_projp)[i + NTOK * CDIM / 4];
    const float4 bb = ((const float4*)bias)[i & 127];
    float4 o;
    o.x = a.x + b.x + bb.x;
    o.y = a.y + b.y + bb.y;
    o.z = a.z + b.z + bb.z;
    o.w = a.w + b.w + bb.w;
    ((float4*)out)[i] = o;
}

// spacer (keeps attn in ncu's captured slot 4)
__device__ float g_dummy[1];
__global__ void dummy_kernel() { if (threadIdx.x == 0) g_dummy[0] = 1.f; }

// ============================================================
// Positional-embedding precompute, split by table (3x parallelism):
//   g_pos[((tbl*8+h)*NTOK + n)*44 + j] = q(h,n,:) . rel_tbl[j,:]
// grid (16, 8, 3) = 384 CTAs; uniform-j broadcast LDS (conflict-free).
// ============================================================
__global__ void __launch_bounds__(256) pos_kernel(
    const float* __restrict__ rel_d, const float* __restrict__ rel_h,
    const float* __restrict__ rel_w)
{
    __shared__ __align__(16) float srel[42 * 64];
    const int tid = threadIdx.x;
    const int tbl = blockIdx.z;
    const float* rel = (tbl == 0) ? rel_w : (tbl == 1) ? rel_h : rel_d;
    {
        float4* s4 = (float4*)srel;
        const float4* r4 = (const float4*)rel;
        for (int i = tid; i < 672; i += 256) s4[i] = r4[i];
    }
    __syncthreads();

    const int h = blockIdx.y;
    const int n = blockIdx.x * 256 + tid;

    float4 q[16];
    const float4* qp = (const float4*)(g_qkv + (size_t)n * QKVW + h * 64);
#pragma unroll
    for (int i = 0; i < 16; i++) q[i] = qp[i];

    const float4* rl = (const float4*)srel;
    float* dst = g_pos + ((size_t)(tbl * 8 + h) * NTOK + n) * 44;
    for (int j4 = 0; j4 < 11; j4++) {
        float res[4];
#pragma unroll
        for (int jj = 0; jj < 4; jj++) {
            const int j = j4 * 4 + jj;
            float a = 0.f, b = 0.f, c = 0.f, d = 0.f;
            if (j < 42) {
                const float4* rr = rl + j * 16;
#pragma unroll
                for (int i = 0; i < 16; i++) {
                    float4 rv = rr[i];
                    a = fmaf(q[i].x, rv.x, a);
                    b = fmaf(q[i].y, rv.y, b);
                    c = fmaf(q[i].z, rv.z, c);
                    d = fmaf(q[i].w, rv.w, d);
                }
            }
            res[jj] = (a + b) + (c + d);
        }
        float4 outv; outv.x = res[0]; outv.y = res[1];
        outv.z = res[2]; outv.w = res[3];
        *(float4*)(dst + j4 * 4) = outv;
    }
}

// ============================================================
// Fused deformable attention — k-dot in half2 (HFMA2), v fp32 accum.
// Record (112B): w fp32 x8 | wh2 x8 | ko x8 | pos
// ============================================================
__device__ __forceinline__ void corner_setup(
    int z, int y, int x, int s, float soz, float soy, float sox,
    int idx[8], float w[8])
{
    const float pz = (float)(z + s / 9 - 1) + soz;
    const float py = (float)(y + (s / 3) % 3 - 1) + soy;
    const float px = (float)(x + s % 3 - 1) + sox;
    const float fz = floorf(pz), fy = floorf(py), fx = floorf(px);
    const float wz = pz - fz, wy = py - fy, wx = px - fx;
    const int iz = (int)fz, iy = (int)fy, ix = (int)fx;
    const int z0 = min(max(iz, 0), 15), z1 = min(max(iz + 1, 0), 15);
    const int y0 = min(max(iy, 0), 15), y1 = min(max(iy + 1, 0), 15);
    const int x0 = min(max(ix, 0), 15), x1 = min(max(ix + 1, 0), 15);
    const float wz0 = ((unsigned)iz < 16u) ? 1.f - wz : 0.f;
    const float wz1 = ((unsigned)(iz + 1) < 16u) ? wz : 0.f;
    const float wy0 = ((unsigned)iy < 16u) ? 1.f - wy : 0.f;
    const float wy1 = ((unsigned)(iy + 1) < 16u) ? wy : 0.f;
    const float wx0 = ((unsigned)ix < 16u) ? 1.f - wx : 0.f;
    const float wx1 = ((unsigned)(ix + 1) < 16u) ? wx : 0.f;
    idx[0] = (z0 * 16 + y0) * 16 + x0;  w[0] = wz0 * wy0 * wx0;
    idx[1] = (z0 * 16 + y0) * 16 + x1;  w[1] = wz0 * wy0 * wx1;
    idx[2] = (z0 * 16 + y1) * 16 + x0;  w[2] = wz0 * wy1 * wx0;
    idx[3] = (z0 * 16 + y1) * 16 + x1;  w[3] = wz0 * wy1 * wx1;
    idx[4] = (z1 * 16 + y0) * 16 + x0;  w[4] = wz1 * wy0 * wx0;
    idx[5] = (z1 * 16 + y0) * 16 + x1;  w[5] = wz1 * wy0 * wx1;
    idx[6] = (z1 * 16 + y1) * 16 + x0;  w[6] = wz1 * wy1 * wx0;
    idx[7] = (z1 * 16 + y1) * 16 + x1;  w[7] = wz1 * wy1 * wx1;
}

#define GREC 28   // floats per geometry record (112B)

__global__ void __launch_bounds__(256) attn_kernel()
{
    __shared__ __align__(16) float sgeo[8 * NSAMP * GREC];  // 24.2 KB
    const int tid = threadIdx.x;
    const int warp = tid >> 5;
    const int lane = tid & 31;
    const int n = blockIdx.x * 8 + warp;
    const int h = blockIdx.y;
    const int z = n >> 8, y = (n >> 4) & 15, x = n & 15;
    const int c0 = lane << 1;

    // ---- phase 1: lane-parallel geometry + pos + half2 weights ----
    float* grec = sgeo + warp * NSAMP * GREC;
    if (lane < NSAMP) {
        const float* offp = g_off + ((size_t)h * NTOK + n) * 81 + lane * 3;
        const float oz = offp[0], oy = offp[1], ox = offp[2];
        int idx[8]; float w[8];
        corner_setup(z, y, x, lane, oz, oy, ox, idx, w);
        const int j = 15 + lane - x;
        const int nzx = (z * 16 + x) * 16 + y;
        const int nxz = (x * 16 + z) * 16 + y;
        const float pos =
            g_pos[((size_t)h * NTOK + n) * 44 + j] +
            g_pos[((size_t)(8 + h) * NTOK + nzx) * 44 + j] +
            g_pos[((size_t)(16 + h) * NTOK + nxz) * 44 + j];
        float* r = grec + lane * GREC;
        *(float4*)(r + 0) = make_float4(w[0], w[1], w[2], w[3]);
        *(float4*)(r + 4) = make_float4(w[4], w[5], w[6], w[7]);
        uint4 whv0, whv1;
        union { __half2 h2; uint32_t u; } cw;
#define WH(c) (cw.h2 = __floats2half2_rn(w[c], w[c]), cw.u)
        whv0.x = WH(0); whv0.y = WH(1); whv0.z = WH(2); whv0.w = WH(3);
        whv1.x = WH(4); whv1.y = WH(5); whv1.z = WH(6); whv1.w = WH(7);
#undef WH
        *(uint4*)(r + 8)  = whv0;
        *(uint4*)(r + 12) = whv1;
        int4 ka, kb4;
        ka.x  = idx[0] * 6144; ka.y  = idx[1] * 6144;
        ka.z  = idx[2] * 6144; ka.w  = idx[3] * 6144;
        kb4.x = idx[4] * 6144; kb4.y = idx[5] * 6144;
        kb4.z = idx[6] * 6144; kb4.w = idx[7] * 6144;
        *(int4*)(r + 16) = ka;
        *(int4*)(r + 20) = kb4;
        r[24] = pos;
    }
    __syncwarp();

    // ---- phase 2: per-sample loop ----
    const float2 qa = *(const float2*)(g_qkv + (size_t)n * QKVW + h * 64 + c0);
    const __half2 qh2 = __floats2half2_rn(qa.x, qa.y);
    const char* kbase = (const char*)g_qkv + 4096 + (h * 64 + c0) * 2;

    float ssum = 0.f, a0 = 0.f, a1 = 0.f;

#pragma unroll 3
    for (int s = 0; s < NSAMP; s++) {
        const float* r = grec + s * GREC;
        const float4 wa = *(const float4*)(r + 0);
        const float4 wb = *(const float4*)(r + 4);
        const uint4  wha = *(const uint4*)(r + 8);
        const uint4  whb = *(const uint4*)(r + 12);
        const int4   ka = *(const int4*)(r + 16);
        const int4   kc4 = *(const int4*)(r + 20);
        const float pos = r[24];
        const float w[8] = {wa.x, wa.y, wa.z, wa.w, wb.x, wb.y, wb.z, wb.w};
        const uint32_t whu[8] = {wha.x, wha.y, wha.z, wha.w,
                                 whb.x, whb.y, whb.z, whb.w};
        const int ko[8] = {ka.x, ka.y, ka.z, ka.w, kc4.x, kc4.y, kc4.z, kc4.w};

        __half2 kh[8], vh[8];
#pragma unroll
        for (int c = 0; c < 8; c++) {
            const char* p = kbase + ko[c];
            kh[c] = *(const __half2*)p;
            vh[c] = *(const __half2*)(p + 1024);
        }

        // k dot in half2: acc += (k*q) * w  per corner (2 instr each)
        __half2 acch = __float2half2_rn(0.f);
#pragma unroll
        for (int c = 0; c < 8; c++) {
            union { uint32_t u; __half2 h2; } wc; wc.u = whu[c];
            acch = __hfma2(__hmul2(kh[c], qh2), wc.h2, acch);
        }
        const float2 pf = __half22float2(acch);
        float part = pf.x + pf.y;

#pragma unroll
        for (int o = 16; o > 0; o >>= 1)
            part += __shfl_xor_sync(0xffffffffu, part, o);

        const float val = 0.125f * part + pos;
        const float pr = __expf(val);
        ssum += pr;

#pragma unroll
        for (int c = 0; c < 8; c++) {
            const float2 vf = __half22float2(vh[c]);
            const float pw = pr * w[c];
            a0 = fmaf(pw, vf.x, a0);
            a1 = fmaf(pw, vf.y, a1);
        }
    }

    const float inv = 1.f / ssum;
    float2 res; res.x = a0 * inv; res.y = a1 * inv;
    *(float2*)(g_ao + (size_t)n * CDIM + h * 64 + c0) = res;
}

// ============================================================
extern "C" void kernel_launch(void* const* d_in, const int* in_sizes, int n_in,
                              void* d_out, int out_size)
{
    const float* x      = (const float*)d_in[0];
    const float* w_qkv  = (const float*)d_in[1];
    const float* w_proj = (const float*)d_in[2];
    const float* b_proj = (const float*)d_in[3];
    const float* w_off  = (const float*)d_in[4];
    const float* rel_d  = (const float*)d_in[5];
    const float* rel_h  = (const float*)d_in[6];
    const float* rel_w  = (const float*)d_in[7];
    float* out = (float*)d_out;

    float *ao_p, *pp_p;
    cudaGetSymbolAddress((void**)&ao_p, g_ao);
    cudaGetSymbolAddress((void**)&pp_p, g_projp);

    // 1) fused qkv GEMM (384 blocks) + offsets (128 blocks)
    qkv_offset_kernel<<<512, 256>>>(x, w_qkv, w_off);

    // 2) positional-embedding precompute, tbl-split (384 CTAs)
    pos_kernel<<<dim3(NTOK / 256, NHEAD, 3), 256>>>(rel_d, rel_h, rel_w);

    // 3) spacer (attn stays in ncu slot 4)
    dummy_kernel<<<1, 32>>>();

    // 4) fused deformable attention (half2 k-dot)
    attn_kernel<<<dim3(NTOK / 8, NHEAD), 256>>>();

    // 5) proj split-K=2 (256 CTAs)
    sgemm_proj<<<dim3(CDIM / 128, NTOK / 128, 2), 256>>>(ao_p, w_proj, pp_p);

    // 6) merge partials + bias -> out
    proj_merge<<<NTOK * CDIM / 4 / 256, 256>>>(b_proj, out);
}

// round 16
// speedup vs baseline: 1.2568x; 1.0289x over previous
#include <cuda_runtime.h>
#include <cuda_fp16.h>
#include <math.h>
#include <stdint.h>

typedef unsigned long long ull;

// Problem constants (fixed shapes)
#define NTOK   4096
#define NHEAD  8
#define NSAMP  27
#define CDIM   512
#define QKVW   1536

// -------- scratch (device globals; no allocations allowed) --------
// g_qkv row layout (6144 B): q fp32 [0,2048) | k fp16 [4096,5120) | v fp16 [5120,6144)
__device__ float  g_qkv  [NTOK * QKVW];
__device__ float  g_off  [NHEAD * NTOK * 81];      // offsets per (h,n)
__device__ float  g_ao   [NTOK * CDIM];            // attention output fp32
__device__ float  g_pos  [3 * NHEAD * NTOK * 44];  // pos-emb tables (44-stride)
__device__ float  g_projp[2 * NTOK * CDIM];        // proj split-k partials

// Packed fp32x2 FMA (Blackwell): d = a*b + d
#define FMA2(d, a, b) \
    asm("fma.rn.f32x2 %0, %1, %2, %0;" : "+l"(d) : "l"(a), "l"(b))
#define PACK2(d, s) \
    asm("mov.b64 %0, {%1, %1};" : "=l"(d) : "f"(s))

// ============================================================
// qkv GEMM body (R10-proven v1 core), fused with offset kernel below.
// ============================================================
__device__ __forceinline__ void qkv_body(
    const float* __restrict__ A, const float* __restrict__ W,
    int bx, int by)
{
    __shared__ __align__(16) float As[2][8][132];
    __shared__ __align__(16) float Ws[2][8][132];

    const int tid = threadIdx.x;
    const int tx = tid & 15;
    const int ty = tid >> 4;
    const int m0 = by * 128, n0 = bx * 128;
    const int alr = tid >> 1;
    const int alk = (tid & 1) * 4;
    const int wlr = tid >> 1, wlk = (tid & 1) * 4;

    const float* Ap = A + (size_t)(m0 + alr) * CDIM + alk;
    const float* Wp = W + (size_t)(n0 + wlr) * CDIM + wlk;
    float* C = g_qkv;

    ull acc[8][4];
#pragma unroll
    for (int i = 0; i < 8; i++)
#pragma unroll
        for (int j = 0; j < 4; j++) acc[i][j] = 0ULL;

    {
        float4 t = *(const float4*)Ap;
        float4 wv = *(const float4*)Wp;
        As[0][alk + 0][alr] = t.x; As[0][alk + 1][alr] = t.y;
        As[0][alk + 2][alr] = t.z; As[0][alk + 3][alr] = t.w;
        Ws[0][wlk + 0][wlr] = wv.x; Ws[0][wlk + 1][wlr] = wv.y;
        Ws[0][wlk + 2][wlr] = wv.z; Ws[0][wlk + 3][wlr] = wv.w;
    }
    __syncthreads();

    const int nst = CDIM >> 3;
    for (int st = 0; st < nst; st++) {
        const int buf = st & 1;
        const bool has = (st + 1) < nst;
        float4 t2, wv2;
        if (has) {
            t2 = *(const float4*)(Ap + (st + 1) * 8);
            wv2 = *(const float4*)(Wp + (st + 1) * 8);
        }
#pragma unroll
        for (int kk = 0; kk < 8; kk++) {
            float af[8];
            *(float4*)&af[0] = *(const float4*)&As[buf][kk][ty * 8];
            *(float4*)&af[4] = *(const float4*)&As[buf][kk][ty * 8 + 4];
            ull a2[8];
#pragma unroll
            for (int i = 0; i < 8; i++) PACK2(a2[i], af[i]);
            ulonglong2 q0 = *(const ulonglong2*)&Ws[buf][kk][tx * 8];
            ulonglong2 q1 = *(const ulonglong2*)&Ws[buf][kk][tx * 8 + 4];
            ull b2[4] = {q0.x, q0.y, q1.x, q1.y};
#pragma unroll
            for (int i = 0; i < 8; i++) {
                FMA2(acc[i][0], a2[i], b2[0]);
                FMA2(acc[i][1], a2[i], b2[1]);
                FMA2(acc[i][2], a2[i], b2[2]);
                FMA2(acc[i][3], a2[i], b2[3]);
            }
        }
        if (has) {
            const int nb = buf ^ 1;
            As[nb][alk + 0][alr] = t2.x; As[nb][alk + 1][alr] = t2.y;
            As[nb][alk + 2][alr] = t2.z; As[nb][alk + 3][alr] = t2.w;
            Ws[nb][wlk + 0][wlr] = wv2.x; Ws[nb][wlk + 1][wlr] = wv2.y;
            Ws[nb][wlk + 2][wlr] = wv2.z; Ws[nb][wlk + 3][wlr] = wv2.w;
        }
        __syncthreads();
    }

    const bool half_out = (n0 >= 512);

#pragma unroll
    for (int i = 0; i < 8; i++) {
        union { ull u; float2 f; } p[4];
#pragma unroll
        for (int j = 0; j < 4; j++) p[j].u = acc[i][j];
        float4 o0, o1;
        o0.x = p[0].f.x; o0.y = p[0].f.y;
        o0.z = p[1].f.x; o0.w = p[1].f.y;
        o1.x = p[2].f.x; o1.y = p[2].f.y;
        o1.z = p[3].f.x; o1.w = p[3].f.y;
        const int row = m0 + ty * 8 + i;
        if (!half_out) {
            float* cp = C + (size_t)row * QKVW + n0 + tx * 8;
            *(float4*)cp = o0;
            *(float4*)(cp + 4) = o1;
        } else {
            union { __half2 h2[4]; uint4 u; } hv;
            hv.h2[0] = __float22half2_rn(make_float2(o0.x, o0.y));
            hv.h2[1] = __float22half2_rn(make_float2(o0.z, o0.w));
            hv.h2[2] = __float22half2_rn(make_float2(o1.x, o1.y));
            hv.h2[3] = __float22half2_rn(make_float2(o1.z, o1.w));
            char* rowb = (char*)C + (size_t)row * (QKVW * 4);
            *(uint4*)(rowb + 4096 + ((n0 - 512) + tx * 8) * 2) = hv.u;
        }
    }
}

__device__ __forceinline__ void offset_body(
    const float* __restrict__ x, const float* __restrict__ w_off, int b)
{
    __shared__ float sw[81 * 64];
    const int tid = threadIdx.x;
    for (int i = tid; i < 81 * 64 / 4; i += 256)
        ((float4*)sw)[i] = ((const float4*)w_off)[i];
    __syncthreads();

    const int g = b * 256 + tid;
    const int h = g & 7, n = g >> 3;

    float4 xr[16];
    const float4* xp = (const float4*)(x + (size_t)n * CDIM + h * 64);
#pragma unroll
    for (int i = 0; i < 16; i++) xr[i] = xp[i];

    float* op = g_off + ((size_t)h * NTOK + n) * 81;
    for (int c = 0; c < 81; c++) {
        const float4* wp = (const float4*)(sw + c * 64);
        float acc = 0.f;
#pragma unroll
        for (int i = 0; i < 16; i++) {
            float4 w4 = wp[i];
            acc = fmaf(w4.x, xr[i].x, acc);
            acc = fmaf(w4.y, xr[i].y, acc);
            acc = fmaf(w4.z, xr[i].z, acc);
            acc = fmaf(w4.w, xr[i].w, acc);
        }
        op[c] = acc;
    }
}

__global__ void __launch_bounds__(256, 2) qkv_offset_kernel(
    const float* __restrict__ x, const float* __restrict__ w_qkv,
    const float* __restrict__ w_off)
{
    const int b = blockIdx.x;
    if (b < 384) {
        qkv_body(x, w_qkv, b % 12, b / 12);
    } else {
        offset_body(x, w_off, b - 384);
    }
}

// ============================================================
// proj GEMM (split-K=2, R14-proven) + merge
// ============================================================
__global__ void __launch_bounds__(256, 2) sgemm_proj(
    const float* __restrict__ A, const float* __restrict__ W,
    float* __restrict__ C)
{
    constexpr int K = CDIM / 2;

    __shared__ __align__(16) float As[2][8][132];
    __shared__ __align__(16) float Ws[2][8][132];

    const int tid = threadIdx.x;
    const int tx = tid & 15;
    const int ty = tid >> 4;
    const int m0 = blockIdx.y * 128, n0 = blockIdx.x * 128;
    const int zk = blockIdx.z * K;
    const int alr = tid >> 1;
    const int alk = (tid & 1) * 4;

    const float* Ap = A + (size_t)(m0 + alr) * CDIM + alk + zk;
    const float* Wp = W + (size_t)(n0 + alr) * CDIM + alk + zk;
    C += (size_t)NTOK * CDIM * blockIdx.z;

    ull acc[8][4];
#pragma unroll
    for (int i = 0; i < 8; i++)
#pragma unroll
        for (int j = 0; j < 4; j++) acc[i][j] = 0ULL;

    {
        float4 t = *(const float4*)Ap;
        float4 wv = *(const float4*)Wp;
        As[0][alk + 0][alr] = t.x; As[0][alk + 1][alr] = t.y;
        As[0][alk + 2][alr] = t.z; As[0][alk + 3][alr] = t.w;
        Ws[0][alk + 0][alr] = wv.x; Ws[0][alk + 1][alr] = wv.y;
        Ws[0][alk + 2][alr] = wv.z; Ws[0][alk + 3][alr] = wv.w;
    }
    __syncthreads();

    const int nst = K >> 3;
    for (int st = 0; st < nst; st++) {
        const int buf = st & 1;
        const bool has = (st + 1) < nst;
        float4 t2, wv2;
        if (has) {
            t2 = *(const float4*)(Ap + (st + 1) * 8);
            wv2 = *(const float4*)(Wp + (st + 1) * 8);
        }
#pragma unroll
        for (int kk = 0; kk < 8; kk++) {
            float af[8];
            *(float4*)&af[0] = *(const float4*)&As[buf][kk][ty * 8];
            *(float4*)&af[4] = *(const float4*)&As[buf][kk][ty * 8 + 4];
            ull a2[8];
#pragma unroll
            for (int i = 0; i < 8; i++) PACK2(a2[i], af[i]);
            ulonglong2 q0 = *(const ulonglong2*)&Ws[buf][kk][tx * 8];
            ulonglong2 q1 = *(const ulonglong2*)&Ws[buf][kk][tx * 8 + 4];
            ull b2[4] = {q0.x, q0.y, q1.x, q1.y};
#pragma unroll
            for (int i = 0; i < 8; i++) {
                FMA2(acc[i][0], a2[i], b2[0]);
                FMA2(acc[i][1], a2[i], b2[1]);
                FMA2(acc[i][2], a2[i], b2[2]);
                FMA2(acc[i][3], a2[i], b2[3]);
            }
        }
        if (has) {
            const int nb = buf ^ 1;
            As[nb][alk + 0][alr] = t2.x; As[nb][alk + 1][alr] = t2.y;
            As[nb][alk + 2][alr] = t2.z; As[nb][alk + 3][alr] = t2.w;
            Ws[nb][alk + 0][alr] = wv2.x; Ws[nb][alk + 1][alr] = wv2.y;
            Ws[nb][alk + 2][alr] = wv2.z; Ws[nb][alk + 3][alr] = wv2.w;
        }
        __syncthreads();
    }

#pragma unroll
    for (int i = 0; i < 8; i++) {
        union { ull u; float2 f; } p[4];
#pragma unroll
        for (int j = 0; j < 4; j++) p[j].u = acc[i][j];
        float4 o0, o1;
        o0.x = p[0].f.x; o0.y = p[0].f.y;
        o0.z = p[1].f.x; o0.w = p[1].f.y;
        o1.x = p[2].f.x; o1.y = p[2].f.y;
        o1.z = p[3].f.x; o1.w = p[3].f.y;
        float* cp = C + (size_t)(m0 + ty * 8 + i) * CDIM + n0 + tx * 8;
        *(float4*)cp = o0;
        *(float4*)(cp + 4) = o1;
    }
}

__global__ void __launch_bounds__(256) proj_merge(
    const float* __restrict__ bias, float* __restrict__ out)
{
    const int i = blockIdx.x * 256 + threadIdx.x;
    const float4 a = ((const float4*)g_projp)[i];
    const float4 b = ((const float4*)g_projp)[i + NTOK * CDIM / 4];
    const float4 bb = ((const float4*)bias)[i & 127];
    float4 o;
    o.x = a.x + b.x + bb.x;
    o.y = a.y + b.y + bb.y;
    o.z = a.z + b.z + bb.z;
    o.w = a.w + b.w + bb.w;
    ((float4*)out)[i] = o;
}

// spacer (keeps attn in ncu's captured slot 4)
__device__ float g_dummy[1];
__global__ void dummy_kernel() { if (threadIdx.x == 0) g_dummy[0] = 1.f; }

// ============================================================
// Positional-embedding precompute, tbl-split (R15-proven).
// ============================================================
__global__ void __launch_bounds__(256) pos_kernel(
    const float* __restrict__ rel_d, const float* __restrict__ rel_h,
    const float* __restrict__ rel_w)
{
    __shared__ __align__(16) float srel[42 * 64];
    const int tid = threadIdx.x;
    const int tbl = blockIdx.z;
    const float* rel = (tbl == 0) ? rel_w : (tbl == 1) ? rel_h : rel_d;
    {
        float4* s4 = (float4*)srel;
        const float4* r4 = (const float4*)rel;
        for (int i = tid; i < 672; i += 256) s4[i] = r4[i];
    }
    __syncthreads();

    const int h = blockIdx.y;
    const int n = blockIdx.x * 256 + tid;

    float4 q[16];
    const float4* qp = (const float4*)(g_qkv + (size_t)n * QKVW + h * 64);
#pragma unroll
    for (int i = 0; i < 16; i++) q[i] = qp[i];

    const float4* rl = (const float4*)srel;
    float* dst = g_pos + ((size_t)(tbl * 8 + h) * NTOK + n) * 44;
    for (int j4 = 0; j4 < 11; j4++) {
        float res[4];
#pragma unroll
        for (int jj = 0; jj < 4; jj++) {
            const int j = j4 * 4 + jj;
            float a = 0.f, b = 0.f, c = 0.f, d = 0.f;
            if (j < 42) {
                const float4* rr = rl + j * 16;
#pragma unroll
                for (int i = 0; i < 16; i++) {
                    float4 rv = rr[i];
                    a = fmaf(q[i].x, rv.x, a);
                    b = fmaf(q[i].y, rv.y, b);
                    c = fmaf(q[i].z, rv.z, c);
                    d = fmaf(q[i].w, rv.w, d);
                }
            }
            res[jj] = (a + b) + (c + d);
        }
        float4 outv; outv.x = res[0]; outv.y = res[1];
        outv.z = res[2]; outv.w = res[3];
        *(float4*)(dst + j4 * 4) = outv;
    }
}

// ============================================================
// Fused deformable attention — 2 tokens/warp, 16 lanes/token,
// lane owns 4 channels. half2 k-dot, fp32 v accumulation.
// Record (80B): w fp32 x8 | k byte-offsets x8 | pos
// ============================================================
__device__ __forceinline__ void corner_setup(
    int z, int y, int x, int s, float soz, float soy, float sox,
    int idx[8], float w[8])
{
    const float pz = (float)(z + s / 9 - 1) + soz;
    const float py = (float)(y + (s / 3) % 3 - 1) + soy;
    const float px = (float)(x + s % 3 - 1) + sox;
    const float fz = floorf(pz), fy = floorf(py), fx = floorf(px);
    const float wz = pz - fz, wy = py - fy, wx = px - fx;
    const int iz = (int)fz, iy = (int)fy, ix = (int)fx;
    const int z0 = min(max(iz, 0), 15), z1 = min(max(iz + 1, 0), 15);
    const int y0 = min(max(iy, 0), 15), y1 = min(max(iy + 1, 0), 15);
    const int x0 = min(max(ix, 0), 15), x1 = min(max(ix + 1, 0), 15);
    const float wz0 = ((unsigned)iz < 16u) ? 1.f - wz : 0.f;
    const float wz1 = ((unsigned)(iz + 1) < 16u) ? wz : 0.f;
    const float wy0 = ((unsigned)iy < 16u) ? 1.f - wy : 0.f;
    const float wy1 = ((unsigned)(iy + 1) < 16u) ? wy : 0.f;
    const float wx0 = ((unsigned)ix < 16u) ? 1.f - wx : 0.f;
    const float wx1 = ((unsigned)(ix + 1) < 16u) ? wx : 0.f;
    idx[0] = (z0 * 16 + y0) * 16 + x0;  w[0] = wz0 * wy0 * wx0;
    idx[1] = (z0 * 16 + y0) * 16 + x1;  w[1] = wz0 * wy0 * wx1;
    idx[2] = (z0 * 16 + y1) * 16 + x0;  w[2] = wz0 * wy1 * wx0;
    idx[3] = (z0 * 16 + y1) * 16 + x1;  w[3] = wz0 * wy1 * wx1;
    idx[4] = (z1 * 16 + y0) * 16 + x0;  w[4] = wz1 * wy0 * wx0;
    idx[5] = (z1 * 16 + y0) * 16 + x1;  w[5] = wz1 * wy0 * wx1;
    idx[6] = (z1 * 16 + y1) * 16 + x0;  w[6] = wz1 * wy1 * wx0;
    idx[7] = (z1 * 16 + y1) * 16 + x1;  w[7] = wz1 * wy1 * wx1;
}

#define GREC 20   // floats per geometry record (80B)

__global__ void __launch_bounds__(256) attn_kernel()
{
    __shared__ __align__(16) float sgeo[8][2][NSAMP][GREC];  // 34.6 KB
    const int tid = threadIdx.x;
    const int warp = tid >> 5;
    const int lane = tid & 31;
    const int t0 = (blockIdx.x * 8 + warp) * 2;
    const int h = blockIdx.y;

    // ---- phase 1: lane-parallel geometry + pos (2 tokens) ----
#pragma unroll
    for (int g2 = 0; g2 < 2; g2++) {
        if (lane < NSAMP) {
            const int n2 = t0 + g2;
            const int z2 = n2 >> 8, y2 = (n2 >> 4) & 15, x2 = n2 & 15;
            const float* offp = g_off + ((size_t)h * NTOK + n2) * 81 + lane * 3;
            const float oz = offp[0], oy = offp[1], ox = offp[2];
            int idx[8]; float w[8];
            corner_setup(z2, y2, x2, lane, oz, oy, ox, idx, w);
            const int j = 15 + lane - x2;
            const int nzx = (z2 * 16 + x2) * 16 + y2;
            const int nxz = (x2 * 16 + z2) * 16 + y2;
            const float pos =
                g_pos[((size_t)h * NTOK + n2) * 44 + j] +
                g_pos[((size_t)(8 + h) * NTOK + nzx) * 44 + j] +
                g_pos[((size_t)(16 + h) * NTOK + nxz) * 44 + j];
            float* r = &sgeo[warp][g2][lane][0];
            *(float4*)(r + 0) = make_float4(w[0], w[1], w[2], w[3]);
            *(float4*)(r + 4) = make_float4(w[4], w[5], w[6], w[7]);
            int4 ka, kb4;
            ka.x  = idx[0] * 6144; ka.y  = idx[1] * 6144;
            ka.z  = idx[2] * 6144; ka.w  = idx[3] * 6144;
            kb4.x = idx[4] * 6144; kb4.y = idx[5] * 6144;
            kb4.z = idx[6] * 6144; kb4.w = idx[7] * 6144;
            *(int4*)(r + 8)  = ka;
            *(int4*)(r + 12) = kb4;
            r[16] = pos;
        }
    }
    __syncwarp();

    // ---- phase 2: 16 lanes per token, lane owns 4 channels ----
    const int gidx = lane >> 4;          // token within warp
    const int l16 = lane & 15;
    const int n = t0 + gidx;
    const int c0 = l16 * 4;

    const float4 qv = *(const float4*)(g_qkv + (size_t)n * QKVW + h * 64 + c0);
    const __half2 qh0 = __floats2half2_rn(qv.x, qv.y);
    const __half2 qh1 = __floats2half2_rn(qv.z, qv.w);
    const char* kbase = (const char*)g_qkv + 4096 + (h * 64 + c0) * 2;
    const float* grec = &sgeo[warp][gidx][0][0];

    float ssum = 0.f;
    float a0 = 0.f, a1 = 0.f, a2 = 0.f, a3 = 0.f;

#pragma unroll 3
    for (int s = 0; s < NSAMP; s++) {
        const float* r = grec + s * GREC;
        const float4 wa = *(const float4*)(r + 0);
        const float4 wb = *(const float4*)(r + 4);
        const int4   ka = *(const int4*)(r + 8);
        const int4   kc4 = *(const int4*)(r + 12);
        const float pos = r[16];
        const float w[8] = {wa.x, wa.y, wa.z, wa.w, wb.x, wb.y, wb.z, wb.w};
        const int ko[8] = {ka.x, ka.y, ka.z, ka.w, kc4.x, kc4.y, kc4.z, kc4.w};

        uint2 kk[8], vv[8];
#pragma unroll
        for (int c = 0; c < 8; c++) {
            const char* p = kbase + ko[c];
            kk[c] = *(const uint2*)p;
            vv[c] = *(const uint2*)(p + 1024);
        }

        // half2 k-dot with per-corner weight
        __half2 acch = __float2half2_rn(0.f);
#pragma unroll
        for (int c = 0; c < 8; c++) {
            union { uint32_t u; __half2 h; } k0, k1;
            k0.u = kk[c].x; k1.u = kk[c].y;
            const __half2 wh2 = __float2half2_rn(w[c]);
            __half2 t = __hmul2(k0.h, qh0);
            t = __hfma2(k1.h, qh1, t);
            acch = __hfma2(t, wh2, acch);
        }
        const float2 pf = __half22float2(acch);
        float part = pf.x + pf.y;

        // reduce over 16-lane group
        part += __shfl_xor_sync(0xffffffffu, part, 8);
        part += __shfl_xor_sync(0xffffffffu, part, 4);
        part += __shfl_xor_sync(0xffffffffu, part, 2);
        part += __shfl_xor_sync(0xffffffffu, part, 1);

        const float val = 0.125f * part + pos;
        const float pr = __expf(val);
        ssum += pr;

        // v accumulate (fp32)
#pragma unroll
        for (int c = 0; c < 8; c++) {
            union { uint32_t u; __half2 h; } v0, v1;
            v0.u = vv[c].x; v1.u = vv[c].y;
            const float2 f0 = __half22float2(v0.h);
            const float2 f1 = __half22float2(v1.h);
            const float pw = pr * w[c];
            a0 = fmaf(pw, f0.x, a0);
            a1 = fmaf(pw, f0.y, a1);
            a2 = fmaf(pw, f1.x, a2);
            a3 = fmaf(pw, f1.y, a3);
        }
    }

    const float inv = 1.f / ssum;
    float4 res;
    res.x = a0 * inv; res.y = a1 * inv;
    res.z = a2 * inv; res.w = a3 * inv;
    *(float4*)(g_ao + (size_t)n * CDIM + h * 64 + c0) = res;
}

// ============================================================
extern "C" void kernel_launch(void* const* d_in, const int* in_sizes, int n_in,
                              void* d_out, int out_size)
{
    const float* x      = (const float*)d_in[0];
    const float* w_qkv  = (const float*)d_in[1];
    const float* w_proj = (const float*)d_in[2];
    const float* b_proj = (const float*)d_in[3];
    const float* w_off  = (const float*)d_in[4];
    const float* rel_d  = (const float*)d_in[5];
    const float* rel_h  = (const float*)d_in[6];
    const float* rel_w  = (const float*)d_in[7];
    float* out = (float*)d_out;

    float *ao_p, *pp_p;
    cudaGetSymbolAddress((void**)&ao_p, g_ao);
    cudaGetSymbolAddress((void**)&pp_p, g_projp);

    // 1) fused qkv GEMM (384 blocks) + offsets (128 blocks)
    qkv_offset_kernel<<<512, 256>>>(x, w_qkv, w_off);

    // 2) positional-embedding precompute, tbl-split (384 CTAs)
    pos_kernel<<<dim3(NTOK / 256, NHEAD, 3), 256>>>(rel_d, rel_h, rel_w);

    // 3) spacer (attn stays in ncu slot 4)
    dummy_kernel<<<1, 32>>>();

    // 4) fused deformable attention (2 tokens/warp)
    attn_kernel<<<dim3(NTOK / 16, NHEAD), 256>>>();

    // 5) proj split-K=2 (256 CTAs)
    sgemm_proj<<<dim3(CDIM / 128, NTOK / 128, 2), 256>>>(ao_p, w_proj, pp_p);

    // 6) merge partials + bias -> out
    proj_merge<<<NTOK * CDIM / 4 / 256, 256>>>(b_proj, out);
}